// round 11
// baseline (speedup 1.0000x reference)
#include <cuda_runtime.h>
#include <cuda_fp16.h>
#include <cstdint>

// ---------------- problem constants ----------------
#define SPATIAL   4096
#define DIM       64
#define NCODES    1024
#define Q_ELEMS   4194304
#define OUT_LOSS_OFF 0
#define OUT_Q_OFF    1
#define OUT_IDX_OFF  (1 + Q_ELEMS)

#define TILE_M    64            // positions per CTA
#define ESTRIDE   72            // halves per row (144B): conflict-free LDS/LDSM
#define BLK_BYTES 2304          // 8 codes x (hi 72 + lo 72) halves x 2B
#define NBLK      32            // code blocks per code-group (256 codes / 8)

// smem layout (byte offsets)
#define SM_BUF    0u            // 4 cg x 3 slots x 2304 = 27648
#define SM_AHI    27648u        // 64 x 72 half = 9216
#define SM_ALO    36864u        // 9216
#define SM_NEB    46080u        // 1024 floats
#define SM_CANDV  50176u        // 4 x 64 floats
#define SM_CANDK  51200u        // 4 x 64 ints
#define SM_SBK    52224u        // 64 ints
#define SM_RED    52480u        // 10 floats
#define SMEM_BYTES 52608

// ---------------- device scratch: E packed per 8-code block ----------------
// block b (codes 8b..8b+7): [hi: 8 rows x 72 halves][lo: 8 rows x 72 halves]
__device__ __align__(16) __half g_epk[NCODES * 144];
__device__ float g_neb[NCODES];     // -0.5 * ||e_k||^2

// ---------------- PTX helpers ----------------
__device__ __forceinline__ uint32_t smem_u32(const void* p) {
    uint32_t a;
    asm("{ .reg .u64 t; cvta.to.shared.u64 t, %1; cvt.u32.u64 %0, t; }" : "=r"(a) : "l"(p));
    return a;
}
#define CP16(dst, src)  asm volatile("cp.async.cg.shared.global [%0], [%1], 16;" :: "r"(dst), "l"(src))
#define CP_COMMIT()     asm volatile("cp.async.commit_group;" ::: "memory")
#define CP_WAIT_ALL()   asm volatile("cp.async.wait_group 0;" ::: "memory")
#define BAR_SYNC(id, n) asm volatile("bar.sync %0, %1;" :: "r"(id), "r"(n) : "memory")

__device__ __forceinline__ void ldsm_x4(uint32_t& r0, uint32_t& r1, uint32_t& r2,
                                        uint32_t& r3, uint32_t addr) {
    asm volatile("ldmatrix.sync.aligned.m8n8.x4.shared.b16 {%0,%1,%2,%3}, [%4];"
                 : "=r"(r0), "=r"(r1), "=r"(r2), "=r"(r3) : "r"(addr));
}
__device__ __forceinline__ void mma_init(float& d0, float& d1, float& d2, float& d3,
                                         uint32_t a0, uint32_t a1, uint32_t a2, uint32_t a3,
                                         uint32_t b0, uint32_t b1, float cx, float cy) {
    asm volatile("mma.sync.aligned.m16n8k16.row.col.f32.f16.f16.f32 "
                 "{%0,%1,%2,%3}, {%4,%5,%6,%7}, {%8,%9}, {%10,%11,%10,%11};"
                 : "=f"(d0), "=f"(d1), "=f"(d2), "=f"(d3)
                 : "r"(a0), "r"(a1), "r"(a2), "r"(a3), "r"(b0), "r"(b1),
                   "f"(cx), "f"(cy));
}
__device__ __forceinline__ void mma_acc(float& d0, float& d1, float& d2, float& d3,
                                        uint32_t a0, uint32_t a1, uint32_t a2, uint32_t a3,
                                        uint32_t b0, uint32_t b1) {
    asm volatile("mma.sync.aligned.m16n8k16.row.col.f32.f16.f16.f32 "
                 "{%0,%1,%2,%3}, {%4,%5,%6,%7}, {%8,%9}, {%0,%1,%2,%3};"
                 : "+f"(d0), "+f"(d1), "+f"(d2), "+f"(d3)
                 : "r"(a0), "r"(a1), "r"(a2), "r"(a3), "r"(b0), "r"(b1));
}

// ---------------------------------------------------------------------------
// Kernel 1: split E into (hi, lo) f16, packed per 8-code block; neb; zero loss.
// ---------------------------------------------------------------------------
__global__ void vq_prep_kernel(const float* __restrict__ emb, float* __restrict__ out) {
    int r = blockIdx.x * blockDim.x + threadIdx.x;
    if (r == 0) out[OUT_LOSS_OFF] = 0.0f;
    if (r >= NCODES) return;
    const float* e = emb + (size_t)r * DIM;
    const int block = r >> 3, pos = r & 7;
    __half* dst = g_epk + (size_t)block * 1152 + pos * ESTRIDE;
    float s = 0.0f;
#pragma unroll
    for (int c = 0; c < DIM; c++) {
        float v = e[c];
        s += v * v;
        __half h = __float2half_rn(v);
        dst[c]       = h;
        dst[576 + c] = __float2half_rn(v - __half2float(h));
    }
    g_neb[r] = -0.5f * s;
}

// ---------------------------------------------------------------------------
// Kernel 2: fused HMMA GEMM + argmin + gather + loss.
// 64 positions/CTA; 8 warps = 2 row-groups (32 rows, 2 slabs) x 4 code-groups
// (256 codes). Per code-group: private 3-slot cp.async ring, producer role
// alternates between the 2 row-group warps; pairwise named-barrier sync only.
// ---------------------------------------------------------------------------
__global__ void __launch_bounds__(256, 2) vq_main_kernel(
    const float* __restrict__ x_in,   // [16,64,64,64] NCHW
    const float* __restrict__ emb,    // [1024,64] f32
    float* __restrict__ out)
{
    extern __shared__ char sm[];
    const uint32_t smb = smem_u32(sm);
    __half* aHi = (__half*)(sm + SM_AHI);
    __half* aLo = (__half*)(sm + SM_ALO);
    float*  sneb  = (float*)(sm + SM_NEB);
    float*  candv = (float*)(sm + SM_CANDV);
    int*    candk = (int*)(sm + SM_CANDK);
    int*    sbk   = (int*)(sm + SM_SBK);
    float*  sred  = (float*)(sm + SM_RED);

    const int t    = threadIdx.x;
    const int lane = t & 31;
    const int w    = t >> 5;
    const int cg   = w & 3;          // code group 0..3 (codes cg*256..+255)
    const int rg   = w >> 2;         // row group 0..1 (rows rg*32..+31)
    const int g    = lane >> 2;
    const int q    = lane & 3;
    const int tile = blockIdx.x;
    const int b_idx = tile >> 6;     // 64 tiles per image
    const int s0    = (tile & 63) * TILE_M;

    const char* esrc = (const char*)g_epk + (size_t)cg * NBLK * BLK_BYTES;
    const uint32_t bufcg = smb + SM_BUF + (uint32_t)cg * 3u * BLK_BYTES;

    // --- prologue prefetch: rg0 loads blk0, rg1 loads blk1 (own cp streams) ---
    {
        const int pb = rg;                        // blk 0 or 1
        const uint32_t dst = bufcg + (uint32_t)pb * BLK_BYTES;
        const char* src = esrc + (size_t)pb * BLK_BYTES;
#pragma unroll
        for (int i = lane; i < 144; i += 32) CP16(dst + 16u * i, src + 16 * i);
        CP_COMMIT();
    }

    // --- stage X tile (64 pos) as split f16; accumulate sum(x^2) ---
    {
        const int p = t & 63, qr = t >> 6;
        const float* xp = x_in + (size_t)b_idx * (DIM * SPATIAL) + s0 + p;
        float n2 = 0.0f;
#pragma unroll
        for (int i = 0; i < 16; i++) {
            int c = qr * 16 + i;
            float v = xp[c * SPATIAL];
            n2 += v * v;
            __half h = __float2half_rn(v);
            aHi[p * ESTRIDE + c] = h;
            aLo[p * ESTRIDE + c] = __float2half_rn(v - __half2float(h));
        }
#pragma unroll
        for (int off = 16; off > 0; off >>= 1)
            n2 += __shfl_down_sync(0xffffffffu, n2, off);
        if (lane == 0) sred[w] = n2;
    }
    // cooperative neb load
    for (int i = t; i < NCODES; i += 256) sneb[i] = g_neb[i];
    __syncthreads();

    // --- extract A fragments (2 slabs: rows m0..m0+15, m0+16..m0+31) ---
    const int m0 = rg * 32;
    uint32_t AH[2][4][4], AL[2][4][4];
#pragma unroll
    for (int sl = 0; sl < 2; sl++) {
        const uint32_t r0 = (uint32_t)(m0 + sl * 16 + g) * ESTRIDE;
        const uint32_t r8 = r0 + 8 * ESTRIDE;
#pragma unroll
        for (int ks = 0; ks < 4; ks++) {
            int c0 = 16 * ks + 2 * q;
            AH[sl][ks][0] = *(const uint32_t*)&aHi[r0 + c0];
            AH[sl][ks][1] = *(const uint32_t*)&aHi[r8 + c0];
            AH[sl][ks][2] = *(const uint32_t*)&aHi[r0 + c0 + 8];
            AH[sl][ks][3] = *(const uint32_t*)&aHi[r8 + c0 + 8];
            AL[sl][ks][0] = *(const uint32_t*)&aLo[r0 + c0];
            AL[sl][ks][1] = *(const uint32_t*)&aLo[r8 + c0];
            AL[sl][ks][2] = *(const uint32_t*)&aLo[r0 + c0 + 8];
            AL[sl][ks][3] = *(const uint32_t*)&aLo[r8 + c0 + 8];
        }
    }

    const uint32_t lmoff = (uint32_t)(((lane & 7) * ESTRIDE + (lane >> 3) * 8) * 2);
    const float* nebcg = sneb + cg * 256 + 2 * q;

    float bv0 = -3.402823466e38f, bv1 = -3.402823466e38f;
    float bv2 = -3.402823466e38f, bv3 = -3.402823466e38f;
    int   bk0 = 0, bk1 = 0, bk2 = 0, bk3 = 0;
    const int kcg = cg * 256;

    int csl = 0;   // compute slot = blk % 3
    for (int blk = 0; blk < NBLK; blk++) {
        const int my_prod = ((blk & 1) == rg);
        if (my_prod) CP_WAIT_ALL();        // my single pending group (this blk)
        BAR_SYNC(cg + 1, 64);              // pair sync: buffer ready

        const uint32_t buf = bufcg + (uint32_t)csl * BLK_BYTES;
        const uint32_t bhi = buf + lmoff;
        const uint32_t blo = buf + 1152u + lmoff;
        uint32_t h0, h1, h2, h3, h4, h5, h6, h7;
        uint32_t l0, l1, l2, l3, l4, l5, l6, l7;
        ldsm_x4(h0, h1, h2, h3, bhi);
        ldsm_x4(h4, h5, h6, h7, bhi + 64u);
        ldsm_x4(l0, l1, l2, l3, blo);
        ldsm_x4(l4, l5, l6, l7, blo + 64u);
        float2 nb = *(const float2*)(nebcg + blk * 8);

        // two independent 12-deep chains (slab 0 / slab 1), shared B frags
        float d0, d1, d2, d3, e0, e1, e2, e3;
        mma_init(d0, d1, d2, d3, AH[0][0][0], AH[0][0][1], AH[0][0][2], AH[0][0][3], h0, h1, nb.x, nb.y);
        mma_init(e0, e1, e2, e3, AH[1][0][0], AH[1][0][1], AH[1][0][2], AH[1][0][3], h0, h1, nb.x, nb.y);
        mma_acc (d0, d1, d2, d3, AH[0][1][0], AH[0][1][1], AH[0][1][2], AH[0][1][3], h2, h3);
        mma_acc (e0, e1, e2, e3, AH[1][1][0], AH[1][1][1], AH[1][1][2], AH[1][1][3], h2, h3);
        mma_acc (d0, d1, d2, d3, AH[0][2][0], AH[0][2][1], AH[0][2][2], AH[0][2][3], h4, h5);
        mma_acc (e0, e1, e2, e3, AH[1][2][0], AH[1][2][1], AH[1][2][2], AH[1][2][3], h4, h5);
        mma_acc (d0, d1, d2, d3, AH[0][3][0], AH[0][3][1], AH[0][3][2], AH[0][3][3], h6, h7);
        mma_acc (e0, e1, e2, e3, AH[1][3][0], AH[1][3][1], AH[1][3][2], AH[1][3][3], h6, h7);
        mma_acc (d0, d1, d2, d3, AH[0][0][0], AH[0][0][1], AH[0][0][2], AH[0][0][3], l0, l1);
        mma_acc (e0, e1, e2, e3, AH[1][0][0], AH[1][0][1], AH[1][0][2], AH[1][0][3], l0, l1);
        mma_acc (d0, d1, d2, d3, AH[0][1][0], AH[0][1][1], AH[0][1][2], AH[0][1][3], l2, l3);
        mma_acc (e0, e1, e2, e3, AH[1][1][0], AH[1][1][1], AH[1][1][2], AH[1][1][3], l2, l3);
        mma_acc (d0, d1, d2, d3, AH[0][2][0], AH[0][2][1], AH[0][2][2], AH[0][2][3], l4, l5);
        mma_acc (e0, e1, e2, e3, AH[1][2][0], AH[1][2][1], AH[1][2][2], AH[1][2][3], l4, l5);
        mma_acc (d0, d1, d2, d3, AH[0][3][0], AH[0][3][1], AH[0][3][2], AH[0][3][3], l6, l7);
        mma_acc (e0, e1, e2, e3, AH[1][3][0], AH[1][3][1], AH[1][3][2], AH[1][3][3], l6, l7);
        mma_acc (d0, d1, d2, d3, AL[0][0][0], AL[0][0][1], AL[0][0][2], AL[0][0][3], h0, h1);
        mma_acc (e0, e1, e2, e3, AL[1][0][0], AL[1][0][1], AL[1][0][2], AL[1][0][3], h0, h1);
        mma_acc (d0, d1, d2, d3, AL[0][1][0], AL[0][1][1], AL[0][1][2], AL[0][1][3], h2, h3);
        mma_acc (e0, e1, e2, e3, AL[1][1][0], AL[1][1][1], AL[1][1][2], AL[1][1][3], h2, h3);
        mma_acc (d0, d1, d2, d3, AL[0][2][0], AL[0][2][1], AL[0][2][2], AL[0][2][3], h4, h5);
        mma_acc (e0, e1, e2, e3, AL[1][2][0], AL[1][2][1], AL[1][2][2], AL[1][2][3], h4, h5);
        mma_acc (d0, d1, d2, d3, AL[0][3][0], AL[0][3][1], AL[0][3][2], AL[0][3][3], h6, h7);
        mma_acc (e0, e1, e2, e3, AL[1][3][0], AL[1][3][1], AL[1][3][2], AL[1][3][3], h6, h7);

        const int k0 = kcg + blk * 8 + 2 * q;
        if (d0 > bv0) { bv0 = d0; bk0 = k0; }
        if (d1 > bv0) { bv0 = d1; bk0 = k0 + 1; }
        if (d2 > bv1) { bv1 = d2; bk1 = k0; }
        if (d3 > bv1) { bv1 = d3; bk1 = k0 + 1; }
        if (e0 > bv2) { bv2 = e0; bk2 = k0; }
        if (e1 > bv2) { bv2 = e1; bk2 = k0 + 1; }
        if (e2 > bv3) { bv3 = e2; bk3 = k0; }
        if (e3 > bv3) { bv3 = e3; bk3 = k0 + 1; }

        // prefetch blk+2 into slot (blk+2)%3 (producer of blk owns blk+2)
        const int nblk = blk + 2;
        if (my_prod && nblk < NBLK) {
            int nsl = csl + 2; if (nsl >= 3) nsl -= 3;
            const uint32_t dst = bufcg + (uint32_t)nsl * BLK_BYTES;
            const char* src = esrc + (size_t)nblk * BLK_BYTES;
#pragma unroll
            for (int i = lane; i < 144; i += 32) CP16(dst + 16u * i, src + 16 * i);
            CP_COMMIT();
        }
        if (++csl == 3) csl = 0;
    }

    // --- quad reduce within warp (tie-break smaller k) ---
#pragma unroll
    for (int m = 1; m < 4; m <<= 1) {
        float v; int k;
        v = __shfl_xor_sync(0xffffffffu, bv0, m); k = __shfl_xor_sync(0xffffffffu, bk0, m);
        if (v > bv0 || (v == bv0 && k < bk0)) { bv0 = v; bk0 = k; }
        v = __shfl_xor_sync(0xffffffffu, bv1, m); k = __shfl_xor_sync(0xffffffffu, bk1, m);
        if (v > bv1 || (v == bv1 && k < bk1)) { bv1 = v; bk1 = k; }
        v = __shfl_xor_sync(0xffffffffu, bv2, m); k = __shfl_xor_sync(0xffffffffu, bk2, m);
        if (v > bv2 || (v == bv2 && k < bk2)) { bv2 = v; bk2 = k; }
        v = __shfl_xor_sync(0xffffffffu, bv3, m); k = __shfl_xor_sync(0xffffffffu, bk3, m);
        if (v > bv3 || (v == bv3 && k < bk3)) { bv3 = v; bk3 = k; }
    }
    if (q == 0) {
        candv[cg * 64 + m0 + g]      = bv0;  candk[cg * 64 + m0 + g]      = bk0;
        candv[cg * 64 + m0 + 8 + g]  = bv1;  candk[cg * 64 + m0 + 8 + g]  = bk1;
        candv[cg * 64 + m0 + 16 + g] = bv2;  candk[cg * 64 + m0 + 16 + g] = bk2;
        candv[cg * 64 + m0 + 24 + g] = bv3;  candk[cg * 64 + m0 + 24 + g] = bk3;
    }
    __syncthreads();

    // --- cross-code-group combine (ascending cg => first occurrence) ---
    if (t < 64) {
        float vb = candv[t]; int kb = candk[t];
#pragma unroll
        for (int c = 1; c < 4; c++) {
            float v = candv[c * 64 + t]; int k = candk[c * 64 + t];
            if (v > vb) { vb = v; kb = k; }
        }
        sbk[t] = kb;
        out[OUT_IDX_OFF + (size_t)b_idx * SPATIAL + s0 + t] = (float)kb;
#pragma unroll
        for (int off = 16; off > 0; off >>= 1)
            vb += __shfl_down_sync(0xffffffffu, vb, off);
        if (lane == 0) sred[8 + (t >> 5)] = vb;
    }
    __syncthreads();

    // --- epilogue: quantized gather (coalesced strided stores) ---
    {
        const int p = t & 63, qr = t >> 6;
        const int bk = sbk[p];
        const float4* er = (const float4*)(emb + (size_t)bk * DIM) + qr * 4;
        float* qo = out + OUT_Q_OFF + (size_t)b_idx * (DIM * SPATIAL) + s0 + p;
#pragma unroll
        for (int j = 0; j < 4; j++) {
            float4 e4 = er[j];
            int c = qr * 16 + 4 * j;
            qo[(c + 0) * SPATIAL] = e4.x;
            qo[(c + 1) * SPATIAL] = e4.y;
            qo[(c + 2) * SPATIAL] = e4.z;
            qo[(c + 3) * SPATIAL] = e4.w;
        }
    }
    if (t == 0) {
        float sx = 0.0f;
#pragma unroll
        for (int i = 0; i < 8; i++) sx += sred[i];
        float sv = sred[8] + sred[9];
        atomicAdd(out + OUT_LOSS_OFF, (sx - 2.0f * sv) * (0.25f / (float)Q_ELEMS));
    }
}

// ---------------------------------------------------------------------------
extern "C" void kernel_launch(void* const* d_in, const int* in_sizes, int n_in,
                              void* d_out, int out_size) {
    const float* x_in = (const float*)d_in[0];
    const float* emb  = (const float*)d_in[1];
    float* out = (float*)d_out;

    cudaFuncSetAttribute(vq_main_kernel,
                         cudaFuncAttributeMaxDynamicSharedMemorySize, SMEM_BYTES);

    vq_prep_kernel<<<NCODES / 256, 256>>>(emb, out);
    vq_main_kernel<<<(16 * SPATIAL) / TILE_M, 256, SMEM_BYTES>>>(x_in, emb, out);
}

// round 12
// speedup vs baseline: 1.0240x; 1.0240x over previous
#include <cuda_runtime.h>
#include <cuda_fp16.h>
#include <cstdint>
#include <cfloat>

// ---------------- problem constants ----------------
#define SPATIAL   4096
#define DIM       64
#define NCODES    1024
#define Q_ELEMS   4194304
#define OUT_LOSS_OFF 0
#define OUT_Q_OFF    1
#define OUT_IDX_OFF  (1 + Q_ELEMS)

#define TILE_M    256           // positions per CTA
#define CHUNK     128           // codes per smem chunk
#define NCHUNKS   (NCODES / CHUNK)
#define ESTRIDE   72            // halves per row (144B): conflict-free LDS/LDSM
#define CAP       16            // candidate list capacity per position

// smem layout (byte offsets)
#define BUF0_OFF   0u           // E-hi chunk buf0 (18432)
#define BUF1_OFF   18432u       // E-hi chunk buf1; also A-hi staging per 128-row pass
#define CHUNK_BYTES 18432u
#define SM_NEB     36864u       // 1024 floats (-0.5||e||^2, all codes)
#define SM_EPS     40960u       // 256 floats (margin per position)
#define SM_SNORM   41984u       // 256 floats (||x||^2 per position)
#define SM_LIST    43008u       // 256 x 16 u16 = 8192
#define SM_CNT     51200u       // 256 u32
#define SM_RED     52224u       // 16 floats
#define SMEM_BYTES 52352

// ---------------- device scratch ----------------
__device__ __align__(16) __half g_ehi[NCODES * ESTRIDE];  // fl16(e), padded rows
__device__ float g_neb[NCODES];     // -0.5 * ||e_k||^2 (fp32)
__device__ int   g_emaxbits;        // max ||e_k|| as float bits

// ---------------- PTX helpers ----------------
__device__ __forceinline__ uint32_t smem_u32(const void* p) {
    uint32_t a;
    asm("{ .reg .u64 t; cvta.to.shared.u64 t, %1; cvt.u32.u64 %0, t; }" : "=r"(a) : "l"(p));
    return a;
}
#define CP16(dst, src)  asm volatile("cp.async.cg.shared.global [%0], [%1], 16;" :: "r"(dst), "l"(src))
#define CP_COMMIT()     asm volatile("cp.async.commit_group;" ::: "memory")
#define CP_WAIT0()      asm volatile("cp.async.wait_group 0;" ::: "memory")

__device__ __forceinline__ void ldsm_x4(uint32_t& r0, uint32_t& r1, uint32_t& r2,
                                        uint32_t& r3, uint32_t addr) {
    asm volatile("ldmatrix.sync.aligned.m8n8.x4.shared.b16 {%0,%1,%2,%3}, [%4];"
                 : "=r"(r0), "=r"(r1), "=r"(r2), "=r"(r3) : "r"(addr));
}
__device__ __forceinline__ void mma_init(float& d0, float& d1, float& d2, float& d3,
                                         uint32_t a0, uint32_t a1, uint32_t a2, uint32_t a3,
                                         uint32_t b0, uint32_t b1, float cx, float cy) {
    asm volatile("mma.sync.aligned.m16n8k16.row.col.f32.f16.f16.f32 "
                 "{%0,%1,%2,%3}, {%4,%5,%6,%7}, {%8,%9}, {%10,%11,%10,%11};"
                 : "=f"(d0), "=f"(d1), "=f"(d2), "=f"(d3)
                 : "r"(a0), "r"(a1), "r"(a2), "r"(a3), "r"(b0), "r"(b1),
                   "f"(cx), "f"(cy));
}
__device__ __forceinline__ void mma_acc(float& d0, float& d1, float& d2, float& d3,
                                        uint32_t a0, uint32_t a1, uint32_t a2, uint32_t a3,
                                        uint32_t b0, uint32_t b1) {
    asm volatile("mma.sync.aligned.m16n8k16.row.col.f32.f16.f16.f32 "
                 "{%0,%1,%2,%3}, {%4,%5,%6,%7}, {%8,%9}, {%0,%1,%2,%3};"
                 : "+f"(d0), "+f"(d1), "+f"(d2), "+f"(d3)
                 : "r"(a0), "r"(a1), "r"(a2), "r"(a3), "r"(b0), "r"(b1));
}

// ---------------------------------------------------------------------------
// Kernel 1: E -> f16 hi (padded rows); neb; Emax; zero loss slot.
// ---------------------------------------------------------------------------
__global__ void vq_prep_kernel(const float* __restrict__ emb, float* __restrict__ out) {
    int r = blockIdx.x * blockDim.x + threadIdx.x;
    if (r == 0) out[OUT_LOSS_OFF] = 0.0f;
    if (r >= NCODES) return;
    const float* e = emb + (size_t)r * DIM;
    float s = 0.0f;
#pragma unroll
    for (int c = 0; c < DIM; c++) {
        float v = e[c];
        s += v * v;
        g_ehi[r * ESTRIDE + c] = __float2half_rn(v);
    }
    g_neb[r] = -0.5f * s;
    atomicMax(&g_emaxbits, __float_as_int(sqrtf(s)));
}

// ---------------------------------------------------------------------------
// Chunk copy: E-hi chunk (18432 B) via cp.async 16B.
// ---------------------------------------------------------------------------
__device__ __forceinline__ void copy_chunk(uint32_t smb, int chunkid, int buf, int t) {
    const uint32_t dst = smb + (buf ? BUF1_OFF : BUF0_OFF);
    const char* src = (const char*)(g_ehi + (size_t)chunkid * CHUNK * ESTRIDE);
#pragma unroll
    for (int i = t; i < 1152; i += 256) CP16(dst + 16u * i, src + (size_t)i * 16);
}

// ---------------------------------------------------------------------------
// Kernel 2: two-pass hi-only HMMA screen + exact rescore + gather + loss.
// ---------------------------------------------------------------------------
__global__ void __launch_bounds__(256, 2) vq_main_kernel(
    const float* __restrict__ x_in,   // [16,64,64,64] NCHW
    const float* __restrict__ emb,    // [1024,64] f32
    float* __restrict__ out)
{
    extern __shared__ char sm[];
    const uint32_t smb = smem_u32(sm);
    __half* aHi = (__half*)(sm + BUF1_OFF);             // A staging == buf1
    float*  sneb  = (float*)(sm + SM_NEB);
    float*  seps  = (float*)(sm + SM_EPS);
    float*  snorm = (float*)(sm + SM_SNORM);
    unsigned short* slist = (unsigned short*)(sm + SM_LIST);
    unsigned int*   scnt  = (unsigned int*)(sm + SM_CNT);
    float*  sred  = (float*)(sm + SM_RED);

    const int t    = threadIdx.x;
    const int lane = t & 31;
    const int w    = t >> 5;
    const int g    = lane >> 2;
    const int q    = lane & 3;
    const int tile = blockIdx.x;
    const int b_idx = tile >> 4;               // 16 tiles per image
    const int s0    = (tile & 15) * TILE_M;
    const float* xbase = x_in + (size_t)b_idx * (DIM * SPATIAL) + s0;

    // kick off chunk 0 into buf0 (overlaps staging)
    copy_chunk(smb, 0, 0, t);
    CP_COMMIT();

    // --- stage X in 2 passes of 128 rows through BUF1; extract A-hi frags ---
    const int m0 = w * 16;
    uint32_t AH[2][4][4];
#pragma unroll
    for (int pass = 0; pass < 2; pass++) {
        const int p = t & 127, ch = t >> 7;
        const float* xp = xbase + pass * 128 + p;
        float n2 = 0.0f;
#pragma unroll
        for (int i = 0; i < 32; i++) {
            int c = ch * 32 + i;
            float v = xp[c * SPATIAL];
            n2 += v * v;
            aHi[p * ESTRIDE + c] = __float2half_rn(v);
        }
        if (ch == 0) snorm[pass * 128 + p] = n2;
        __syncthreads();
        if (ch == 1) snorm[pass * 128 + p] += n2;
        {
            const uint32_t r0 = (uint32_t)(m0 + g) * ESTRIDE;
            const uint32_t r8 = r0 + 8 * ESTRIDE;
#pragma unroll
            for (int ks = 0; ks < 4; ks++) {
                int c0 = 16 * ks + 2 * q;
                AH[pass][ks][0] = *(const uint32_t*)&aHi[r0 + c0];
                AH[pass][ks][1] = *(const uint32_t*)&aHi[r8 + c0];
                AH[pass][ks][2] = *(const uint32_t*)&aHi[r0 + c0 + 8];
                AH[pass][ks][3] = *(const uint32_t*)&aHi[r8 + c0 + 8];
            }
        }
        __syncthreads();   // frags + snorm done before BUF1 reuse / eps
    }
    // margin per position + neb table
    {
        const float Emax = __int_as_float(g_emaxbits);
        seps[t] = 1.954e-3f * sqrtf(snorm[t]) * Emax + 4e-3f;   // 2*eps + slack
        for (int i = t; i < NCODES; i += 256) sneb[i] = g_neb[i];
    }

    const uint32_t lmoff = (uint32_t)(((lane & 7) * ESTRIDE + (lane >> 3) * 8) * 2);
    const int r0i = m0 + g, r1i = m0 + g + 8, r2i = 128 + m0 + g, r3i = 128 + m0 + g + 8;

    float bv0 = -FLT_MAX, bv1 = -FLT_MAX, bv2 = -FLT_MAX, bv3 = -FLT_MAX;
    float thr0 = 0, thr1 = 0, thr2 = 0, thr3 = 0;

    for (int c = 0; c < 2 * NCHUNKS; c++) {
        const int chunkid = c & 7, buf = c & 1, pass2 = c >> 3;
        CP_WAIT0();
        if (c == 8) {
            // finalize pass-1 maxima across quad lanes; thresholds; zero lists
            scnt[t] = 0u;
#pragma unroll
            for (int m = 1; m < 4; m <<= 1) {
                bv0 = fmaxf(bv0, __shfl_xor_sync(0xffffffffu, bv0, m));
                bv1 = fmaxf(bv1, __shfl_xor_sync(0xffffffffu, bv1, m));
                bv2 = fmaxf(bv2, __shfl_xor_sync(0xffffffffu, bv2, m));
                bv3 = fmaxf(bv3, __shfl_xor_sync(0xffffffffu, bv3, m));
            }
            thr0 = bv0 - seps[r0i]; thr1 = bv1 - seps[r1i];
            thr2 = bv2 - seps[r2i]; thr3 = bv3 - seps[r3i];
        }
        __syncthreads();
        if (c + 1 < 2 * NCHUNKS) { copy_chunk(smb, (c + 1) & 7, (c + 1) & 1, t); CP_COMMIT(); }

        const uint32_t bhi = smb + (buf ? BUF1_OFF : BUF0_OFF) + lmoff;
        const float* nebc = sneb + chunkid * CHUNK + 2 * q;
        const int kbase = chunkid * CHUNK;

#pragma unroll 2
        for (int n8 = 0; n8 < CHUNK / 8; n8++) {
            const uint32_t adv = (uint32_t)n8 * 1152u;
            uint32_t h0, h1, h2, h3, h4, h5, h6, h7;
            ldsm_x4(h0, h1, h2, h3, bhi + adv);
            ldsm_x4(h4, h5, h6, h7, bhi + adv + 64u);
            float2 nb = *(const float2*)(nebc + n8 * 8);

            float d0, d1, d2, d3, e0, e1, e2, e3;
            mma_init(d0, d1, d2, d3, AH[0][0][0], AH[0][0][1], AH[0][0][2], AH[0][0][3], h0, h1, nb.x, nb.y);
            mma_init(e0, e1, e2, e3, AH[1][0][0], AH[1][0][1], AH[1][0][2], AH[1][0][3], h0, h1, nb.x, nb.y);
            mma_acc (d0, d1, d2, d3, AH[0][1][0], AH[0][1][1], AH[0][1][2], AH[0][1][3], h2, h3);
            mma_acc (e0, e1, e2, e3, AH[1][1][0], AH[1][1][1], AH[1][1][2], AH[1][1][3], h2, h3);
            mma_acc (d0, d1, d2, d3, AH[0][2][0], AH[0][2][1], AH[0][2][2], AH[0][2][3], h4, h5);
            mma_acc (e0, e1, e2, e3, AH[1][2][0], AH[1][2][1], AH[1][2][2], AH[1][2][3], h4, h5);
            mma_acc (d0, d1, d2, d3, AH[0][3][0], AH[0][3][1], AH[0][3][2], AH[0][3][3], h6, h7);
            mma_acc (e0, e1, e2, e3, AH[1][3][0], AH[1][3][1], AH[1][3][2], AH[1][3][3], h6, h7);

            if (!pass2) {
                bv0 = fmaxf(bv0, fmaxf(d0, d1));
                bv1 = fmaxf(bv1, fmaxf(d2, d3));
                bv2 = fmaxf(bv2, fmaxf(e0, e1));
                bv3 = fmaxf(bv3, fmaxf(e2, e3));
            } else {
                const int k0 = kbase + n8 * 8 + 2 * q;
                if (d0 >= thr0) { unsigned i = atomicAdd(&scnt[r0i], 1u); if (i < CAP) slist[r0i * CAP + i] = (unsigned short)k0; }
                if (d1 >= thr0) { unsigned i = atomicAdd(&scnt[r0i], 1u); if (i < CAP) slist[r0i * CAP + i] = (unsigned short)(k0 + 1); }
                if (d2 >= thr1) { unsigned i = atomicAdd(&scnt[r1i], 1u); if (i < CAP) slist[r1i * CAP + i] = (unsigned short)k0; }
                if (d3 >= thr1) { unsigned i = atomicAdd(&scnt[r1i], 1u); if (i < CAP) slist[r1i * CAP + i] = (unsigned short)(k0 + 1); }
                if (e0 >= thr2) { unsigned i = atomicAdd(&scnt[r2i], 1u); if (i < CAP) slist[r2i * CAP + i] = (unsigned short)k0; }
                if (e1 >= thr2) { unsigned i = atomicAdd(&scnt[r2i], 1u); if (i < CAP) slist[r2i * CAP + i] = (unsigned short)(k0 + 1); }
                if (e2 >= thr3) { unsigned i = atomicAdd(&scnt[r3i], 1u); if (i < CAP) slist[r3i * CAP + i] = (unsigned short)k0; }
                if (e3 >= thr3) { unsigned i = atomicAdd(&scnt[r3i], 1u); if (i < CAP) slist[r3i * CAP + i] = (unsigned short)(k0 + 1); }
            }
        }
    }
    __syncthreads();   // all appends visible

    // --- epilogue: exact fp32 rescore of candidates; idx, gather, loss ---
    {
        const int p = t;
        const float* xp = xbase + p;
        const unsigned cnt = scnt[p];
        float bestv = -FLT_MAX;
        int bestk = 0;
        if (cnt <= CAP) {
            for (unsigned i = 0; i < cnt; i++) {
                const int k = slist[p * CAP + i];
                const float4* er = (const float4*)(emb + (size_t)k * DIM);
                float v = sneb[k];
#pragma unroll
                for (int j = 0; j < 16; j++) {
                    float4 e4 = er[j];
                    int cc = 4 * j;
                    v += xp[(cc + 0) * SPATIAL] * e4.x + xp[(cc + 1) * SPATIAL] * e4.y
                       + xp[(cc + 2) * SPATIAL] * e4.z + xp[(cc + 3) * SPATIAL] * e4.w;
                }
                if (v > bestv || (v == bestv && k < bestk)) { bestv = v; bestk = k; }
            }
        } else {
            // overflow fallback (not expected): full exact scan
            for (int k = 0; k < NCODES; k++) {
                const float4* er = (const float4*)(emb + (size_t)k * DIM);
                float v = sneb[k];
#pragma unroll
                for (int j = 0; j < 16; j++) {
                    float4 e4 = er[j];
                    int cc = 4 * j;
                    v += xp[(cc + 0) * SPATIAL] * e4.x + xp[(cc + 1) * SPATIAL] * e4.y
                       + xp[(cc + 2) * SPATIAL] * e4.z + xp[(cc + 3) * SPATIAL] * e4.w;
                }
                if (v > bestv) { bestv = v; bestk = k; }
            }
        }
        out[OUT_IDX_OFF + (size_t)b_idx * SPATIAL + s0 + p] = (float)bestk;

        // gather + exact loss contribution
        const float4* er = (const float4*)(emb + (size_t)bestk * DIM);
        float* qo = out + OUT_Q_OFF + (size_t)b_idx * (DIM * SPATIAL) + s0 + p;
        float lsum = 0.0f;
#pragma unroll
        for (int j = 0; j < 16; j++) {
            float4 e4 = er[j];
            int cc = 4 * j;
            float x0 = xp[(cc + 0) * SPATIAL], x1 = xp[(cc + 1) * SPATIAL];
            float x2 = xp[(cc + 2) * SPATIAL], x3 = xp[(cc + 3) * SPATIAL];
            qo[(cc + 0) * SPATIAL] = e4.x;
            qo[(cc + 1) * SPATIAL] = e4.y;
            qo[(cc + 2) * SPATIAL] = e4.z;
            qo[(cc + 3) * SPATIAL] = e4.w;
            float u0 = e4.x - x0, u1 = e4.y - x1, u2 = e4.z - x2, u3 = e4.w - x3;
            lsum += u0 * u0 + u1 * u1 + u2 * u2 + u3 * u3;
        }
        lsum *= 0.25f / (float)Q_ELEMS;
#pragma unroll
        for (int off = 16; off > 0; off >>= 1)
            lsum += __shfl_down_sync(0xffffffffu, lsum, off);
        if (lane == 0) sred[w] = lsum;
    }
    __syncthreads();
    if (t == 0) {
        float s = 0.0f;
#pragma unroll
        for (int i = 0; i < 8; i++) s += sred[i];
        atomicAdd(out + OUT_LOSS_OFF, s);
    }
}

// ---------------------------------------------------------------------------
extern "C" void kernel_launch(void* const* d_in, const int* in_sizes, int n_in,
                              void* d_out, int out_size) {
    const float* x_in = (const float*)d_in[0];
    const float* emb  = (const float*)d_in[1];
    float* out = (float*)d_out;

    cudaFuncSetAttribute(vq_main_kernel,
                         cudaFuncAttributeMaxDynamicSharedMemorySize, SMEM_BYTES);

    vq_prep_kernel<<<NCODES / 256, 256>>>(emb, out);
    vq_main_kernel<<<(16 * SPATIAL) / TILE_M, 256, SMEM_BYTES>>>(x_in, emb, out);
}